// round 14
// baseline (speedup 1.0000x reference)
#include <cuda_runtime.h>
#include <cuda_bf16.h>
#include <math.h>
#include <stdint.h>

#define BB 8
#define SS 1024
#define EE 512
#define HH 8
#define DD 64

// ---------------- scratch (__device__ globals; no allocation) ---------------
__device__ __nv_bfloat16 g_qbh[BB*HH*SS*DD];   // projected Q heads bf16 hi/lo
__device__ __nv_bfloat16 g_qbl[BB*HH*SS*DD];
__device__ __nv_bfloat16 g_kbh[BB*HH*SS*DD];   // projected K heads
__device__ __nv_bfloat16 g_kbl[BB*HH*SS*DD];
__device__ __nv_bfloat16 g_vth[BB*HH*DD*SS];   // projected V, TRANSPOSED [z][d][s]
__device__ __nv_bfloat16 g_vtl[BB*HH*DD*SS];
__device__ float         g_sc[64L*SS*SS];      // scores [z][i][j] fp32 (256MB)
__device__ __nv_bfloat16 g_ph[64L*SS*SS];      // probs bf16 hi
__device__ __nv_bfloat16 g_pl[64L*SS*SS];      // probs bf16 lo
__device__ __nv_bfloat16 g_aoh[8192L*512];     // attention out hi
__device__ __nv_bfloat16 g_aol[8192L*512];     // attention out lo

// ---------------- helpers ---------------------------------------------------
__device__ __forceinline__ uint32_t smem_u32(const void* p) {
    uint32_t a;
    asm("{ .reg .u64 t; cvta.to.shared.u64 t, %1; cvt.u32.u64 %0, t; }"
        : "=r"(a) : "l"(p));
    return a;
}
__device__ __forceinline__ void ldsm_x4(uint32_t r[4], uint32_t addr) {
    asm volatile("ldmatrix.sync.aligned.m8n8.x4.shared.b16 {%0,%1,%2,%3}, [%4];"
        : "=r"(r[0]), "=r"(r[1]), "=r"(r[2]), "=r"(r[3]) : "r"(addr));
}
__device__ __forceinline__ void ldsm_x2(uint32_t r[2], uint32_t addr) {
    asm volatile("ldmatrix.sync.aligned.m8n8.x2.shared.b16 {%0,%1}, [%2];"
        : "=r"(r[0]), "=r"(r[1]) : "r"(addr));
}
__device__ __forceinline__ void mma_bf16(float c[4], const uint32_t a[4],
                                         const uint32_t b[2]) {
    asm volatile(
        "mma.sync.aligned.m16n8k16.row.col.f32.bf16.bf16.f32 "
        "{%0,%1,%2,%3}, {%4,%5,%6,%7}, {%8,%9}, {%0,%1,%2,%3};"
        : "+f"(c[0]), "+f"(c[1]), "+f"(c[2]), "+f"(c[3])
        : "r"(a[0]), "r"(a[1]), "r"(a[2]), "r"(a[3]), "r"(b[0]), "r"(b[1]));
}
__device__ __forceinline__ float warpSum(float v) {
    #pragma unroll
    for (int o = 16; o > 0; o >>= 1) v += __shfl_xor_sync(0xffffffffu, v, o);
    return v;
}
// fp32x4 -> bf16 hi/lo pairs (each 8 bytes)
__device__ __forceinline__ void split4(float4 x, __nv_bfloat162& h0,
                                       __nv_bfloat162& h1,
                                       __nv_bfloat162& l0,
                                       __nv_bfloat162& l1) {
    __nv_bfloat16 a = __float2bfloat16(x.x), b = __float2bfloat16(x.y);
    __nv_bfloat16 c = __float2bfloat16(x.z), d = __float2bfloat16(x.w);
    h0 = __nv_bfloat162(a, b);
    h1 = __nv_bfloat162(c, d);
    l0 = __nv_bfloat162(__float2bfloat16(x.x - __bfloat162float(a)),
                        __float2bfloat16(x.y - __bfloat162float(b)));
    l1 = __nv_bfloat162(__float2bfloat16(x.z - __bfloat162float(c)),
                        __float2bfloat16(x.w - __bfloat162float(d)));
}
#define CPASYNC16(dst, src) \
    asm volatile("cp.async.ca.shared.global [%0], [%1], 16;" \
        :: "r"(dst), "l"(src) : "memory")
#define CPCOMMIT() asm volatile("cp.async.commit_group;" ::: "memory")
#define CPWAIT(n)  asm volatile("cp.async.wait_group %0;" :: "n"(n) : "memory")

// ============================================================================
// Tensor-core GEMM (3x bf16 split): C[128,128] = A @ B^T + bias
//   mode 0 (z): A = q/k/v fp32 (converted in staging), B = Wk/Wk/Wv fp32;
//               C -> bf16 hi/lo head layout (z==2: V transposed [z][d][s])
//   mode 1:     A = g_aoh/g_aol bf16, B = Wo fp32; C -> fp32 out
// ============================================================================
#define TPAD 144
#define TSZ  18432     // 128*144
#define GEMM_SMEM (4*TSZ)

__global__ __launch_bounds__(256, 1)
void gemm_bf16(const float* __restrict__ q, const float* __restrict__ k,
               const float* __restrict__ v,
               const float* __restrict__ Wk, const float* __restrict__ Wv,
               const float* __restrict__ Wo,
               const float* __restrict__ bk, const float* __restrict__ bv,
               const float* __restrict__ bo, float* __restrict__ out, int mode)
{
    extern __shared__ char sm[];
    const uint32_t sb = smem_u32(sm);
    const int tid = threadIdx.x;
    const int wid = tid >> 5;
    const int lane = tid & 31;

    const float *X = 0, *W;
    const float* bias;
    __nv_bfloat16 *Ybh = 0, *Ybl = 0;
    int z = 0;
    if (mode == 0) {
        z = blockIdx.z;
        X = (z == 0) ? q : ((z == 1) ? k : v);
        W = (z == 2) ? Wv : Wk;
        bias = (z == 2) ? bv : bk;
        Ybh = (z == 0) ? g_qbh : ((z == 1) ? g_kbh : g_vth);
        Ybl = (z == 0) ? g_qbl : ((z == 1) ? g_kbl : g_vtl);
    } else {
        W = Wo;
        bias = bo;
    }

    const int m0 = blockIdx.x * 128;
    const int n0 = blockIdx.y * 128;
    const int wm = (wid >> 2) * 64;
    const int wn = (wid & 3) * 32;

    const uint32_t sA_h = sb;
    const uint32_t sA_l = sb + TSZ;
    const uint32_t sB_h = sb + 2*TSZ;
    const uint32_t sB_l = sb + 3*TSZ;

    float c[4][4][4];
    #pragma unroll
    for (int a = 0; a < 4; a++)
        #pragma unroll
        for (int b = 0; b < 4; b++)
            #pragma unroll
            for (int d = 0; d < 4; d++) c[a][b][d] = 0.f;

    for (int ch = 0; ch < 8; ch++) {
        __syncthreads();
        if (mode == 0) {
            #pragma unroll
            for (int i = 0; i < 16; i++) {
                int slot = tid + i * 256;          // 0..4095
                int arr2 = slot >> 11;             // 0:A 1:B
                int r    = (slot >> 4) & 127;
                int g    = slot & 15;              // float4 group
                const float* src = arr2 ? W : X;
                int grow = (arr2 ? n0 : m0) + r;
                float4 x = *(const float4*)(src + (long)grow * 512 + ch * 64 + g * 4);
                __nv_bfloat162 h0, h1, l0, l1;
                split4(x, h0, h1, l0, l1);
                char* hb = sm + (arr2 ? 2*TSZ : 0) + r * TPAD + g * 8;
                *(__nv_bfloat162*)(hb)             = h0;
                *(__nv_bfloat162*)(hb + 4)         = h1;
                *(__nv_bfloat162*)(hb + TSZ)       = l0;
                *(__nv_bfloat162*)(hb + TSZ + 4)   = l1;
            }
        } else {
            #pragma unroll
            for (int i = 0; i < 16; i++) {
                int slot = tid + i * 256;
                if (slot < 2048) {                 // A: copy bf16 hi/lo
                    int arr = slot >> 10;
                    int r   = (slot >> 3) & 127;
                    int cg  = slot & 7;
                    const __nv_bfloat16* src = arr ? g_aol : g_aoh;
                    uint4 v4 = *(const uint4*)(src + (long)(m0 + r) * 512
                                               + ch * 64 + cg * 8);
                    *(uint4*)(sm + arr * TSZ + r * TPAD + cg * 16) = v4;
                } else {                           // B: Wo fp32 -> hi/lo
                    int s2 = slot - 2048;
                    int r  = (s2 >> 4) & 127;
                    int g  = s2 & 15;
                    float4 x = *(const float4*)(W + (long)(n0 + r) * 512
                                                + ch * 64 + g * 4);
                    __nv_bfloat162 h0, h1, l0, l1;
                    split4(x, h0, h1, l0, l1);
                    char* hb = sm + 2*TSZ + r * TPAD + g * 8;
                    *(__nv_bfloat162*)(hb)           = h0;
                    *(__nv_bfloat162*)(hb + 4)       = h1;
                    *(__nv_bfloat162*)(hb + TSZ)     = l0;
                    *(__nv_bfloat162*)(hb + TSZ + 4) = l1;
                }
            }
        }
        __syncthreads();

        #pragma unroll
        for (int ks = 0; ks < 4; ks++) {
            uint32_t bh[4][2], bl[4][2];
            #pragma unroll
            for (int ni = 0; ni < 4; ni++) {
                uint32_t addr = (uint32_t)((wn + ni*8 + (lane & 7)) * TPAD
                               + (ks*16 + ((lane >> 3) & 1) * 8) * 2);
                ldsm_x2(bh[ni], sB_h + addr);
                ldsm_x2(bl[ni], sB_l + addr);
            }
            #pragma unroll
            for (int mi = 0; mi < 4; mi++) {
                uint32_t addr = (uint32_t)((wm + mi*16 + (lane & 15)) * TPAD
                               + (ks*16 + (lane >> 4) * 8) * 2);
                uint32_t ah[4], al[4];
                ldsm_x4(ah, sA_h + addr);
                ldsm_x4(al, sA_l + addr);
                #pragma unroll
                for (int ni = 0; ni < 4; ni++) {
                    mma_bf16(c[mi][ni], ah, bh[ni]);
                    mma_bf16(c[mi][ni], ah, bl[ni]);
                    mma_bf16(c[mi][ni], al, bh[ni]);
                }
            }
        }
    }

    const int qrow = lane >> 2;
    const int qcol = (lane & 3) * 2;
    #pragma unroll
    for (int mi = 0; mi < 4; mi++) {
        #pragma unroll
        for (int ni = 0; ni < 4; ni++) {
            #pragma unroll
            for (int half = 0; half < 2; half++) {
                int m  = m0 + wm + mi*16 + qrow + half*8;
                int cn = n0 + wn + ni*8 + qcol;
                float x0 = c[mi][ni][half*2 + 0] + bias[cn];
                float x1 = c[mi][ni][half*2 + 1] + bias[cn + 1];
                __nv_bfloat16 h0 = __float2bfloat16(x0);
                __nv_bfloat16 h1 = __float2bfloat16(x1);
                __nv_bfloat16 l0 = __float2bfloat16(x0 - __bfloat162float(h0));
                __nv_bfloat16 l1 = __float2bfloat16(x1 - __bfloat162float(h1));
                if (mode == 0) {
                    int b = m >> 10, s = m & 1023;
                    int h = cn >> 6, d = cn & 63;
                    if (z == 2) {   // V: transposed [z][d][s]
                        long ti = ((long)(b*HH + h) * DD + d) * SS + s;
                        Ybh[ti] = h0;      Ybl[ti] = l0;
                        Ybh[ti + SS] = h1; Ybl[ti + SS] = l1;
                    } else {
                        long idx = (((long)(b*HH + h)) * SS + s) * DD + d;
                        *(__nv_bfloat162*)&Ybh[idx] = __nv_bfloat162(h0, h1);
                        *(__nv_bfloat162*)&Ybl[idx] = __nv_bfloat162(l0, l1);
                    }
                } else {
                    *(float2*)&out[(long)m * 512 + cn] = make_float2(x0, x1);
                }
            }
        }
    }
}

// ============================================================================
// Scores kernel: triangular grid — blockIdx.x = linear causal tile index.
// ============================================================================
#define SCORES_SMEM (4*TSZ)
#define NTILES 36     // 8*9/2

__global__ __launch_bounds__(256, 1)
void scores_kernel()
{
    const int t = blockIdx.x, z = blockIdx.y;
    int it = (int)((sqrtf(8.f * t + 1.f) - 1.f) * 0.5f);
    while ((it + 1) * (it + 2) / 2 <= t) ++it;
    while (it * (it + 1) / 2 > t) --it;
    const int jt = t - it * (it + 1) / 2;

    extern __shared__ char sm[];
    const uint32_t sb = smem_u32(sm);
    const int tid = threadIdx.x;
    const int wid = tid >> 5;
    const int lane = tid & 31;

    const long base = (long)z * SS * DD;
    const __nv_bfloat16* Qh = g_qbh + base;
    const __nv_bfloat16* Ql = g_qbl + base;
    const __nv_bfloat16* Kh = g_kbh + base;
    const __nv_bfloat16* Kl = g_kbl + base;

    const int m0 = it * 128;
    const int n0 = jt * 128;
    const int wm = (wid >> 2) * 64;
    const int wn = (wid & 3) * 32;

    #pragma unroll
    for (int i = 0; i < 16; i++) {
        int slot = tid + i * 256;
        int arr  = slot >> 10;
        int r    = (slot >> 3) & 127;
        int cg   = slot & 7;
        const __nv_bfloat16* src =
            (arr == 0) ? Qh : ((arr == 1) ? Ql : ((arr == 2) ? Kh : Kl));
        int grow = ((arr < 2) ? m0 : n0) + r;
        uint4 v4 = *(const uint4*)(src + (long)grow * DD + cg * 8);
        *(uint4*)(sm + arr * TSZ + r * TPAD + cg * 16) = v4;
    }
    __syncthreads();

    float c[4][4][4];
    #pragma unroll
    for (int a = 0; a < 4; a++)
        #pragma unroll
        for (int b = 0; b < 4; b++)
            #pragma unroll
            for (int d = 0; d < 4; d++) c[a][b][d] = 0.f;

    #pragma unroll
    for (int ks = 0; ks < 4; ks++) {
        uint32_t bh[4][2], bl[4][2];
        #pragma unroll
        for (int ni = 0; ni < 4; ni++) {
            uint32_t addr = (uint32_t)((wn + ni*8 + (lane & 7)) * TPAD
                           + (ks*16 + ((lane >> 3) & 1) * 8) * 2);
            ldsm_x2(bh[ni], sb + 2*TSZ + addr);
            ldsm_x2(bl[ni], sb + 3*TSZ + addr);
        }
        #pragma unroll
        for (int mi = 0; mi < 4; mi++) {
            uint32_t addr = (uint32_t)((wm + mi*16 + (lane & 15)) * TPAD
                           + (ks*16 + (lane >> 4) * 8) * 2);
            uint32_t ah[4], al[4];
            ldsm_x4(ah, sb + addr);
            ldsm_x4(al, sb + TSZ + addr);
            #pragma unroll
            for (int ni = 0; ni < 4; ni++) {
                mma_bf16(c[mi][ni], ah, bh[ni]);
                mma_bf16(c[mi][ni], ah, bl[ni]);
                mma_bf16(c[mi][ni], al, bh[ni]);
            }
        }
    }

    float* dst = g_sc + ((long)z << 20);
    const int qrow = lane >> 2;
    const int qcol = (lane & 3) * 2;
    #pragma unroll
    for (int mi = 0; mi < 4; mi++) {
        #pragma unroll
        for (int ni = 0; ni < 4; ni++) {
            #pragma unroll
            for (int half = 0; half < 2; half++) {
                int m  = m0 + wm + mi*16 + qrow + half*8;
                int cn = n0 + wn + ni*8 + qcol;
                float2 o;
                o.x = c[mi][ni][half*2 + 0] * 0.125f;
                o.y = c[mi][ni][half*2 + 1] * 0.125f;
                *(float2*)&dst[(long)m * SS + cn] = o;
            }
        }
    }
}

// ============================================================================
// Softmax kernel v5 (R11): smem-row-resident, no max-subtraction, 3 passes.
// ============================================================================
__global__ __launch_bounds__(256)
void softmax_kernel(const float* __restrict__ gammas)
{
    __shared__ float rows[8][1024];
    const int tid = threadIdx.x;
    const int w = tid >> 5;
    const int lane = tid & 31;
    float* row = rows[w];

    const long gr = (long)(gridDim.x - 1 - blockIdx.x) * 8 + w;
    const int z = (int)(gr >> 10);
    const int i = (int)(gr & 1023);
    const long rbase = ((long)z << 20) + ((long)i << 10);
    __nv_bfloat16* dh = g_ph + rbase;
    __nv_bfloat16* dl = g_pl + rbase;

    if (i == 0) {
        if (lane < 16) {
            *(uint4*)(dh + lane * 8) = make_uint4(0u, 0u, 0u, 0u);
            *(uint4*)(dl + lane * 8) = make_uint4(0u, 0u, 0u, 0u);
        }
        return;
    }

    const float gamma = -log1pf(expf(gammas[z & 7]));
    const float fi = (float)i;
    const int ci = i >> 7;
    const int nch = ci + 1;

    // ---- P1: load -> smem, exp + sum (mask only in chunk ci) ----
    float sum = 0.f;
    for (int c = 0; c < nch; c++) {
        int j = c * 128 + lane * 4;
        float4 x = *(const float4*)(g_sc + rbase + j);
        *(float4*)&row[j] = x;
        if (c < ci) {
            sum += (__expf(x.x) + __expf(x.y)) + (__expf(x.z) + __expf(x.w));
        } else {
            float fj = (float)j;
            float e0 = (fj       <= fi) ? __expf(x.x) : 0.f;
            float e1 = (fj + 1.f <= fi) ? __expf(x.y) : 0.f;
            float e2 = (fj + 2.f <= fi) ? __expf(x.z) : 0.f;
            float e3 = (fj + 3.f <= fi) ? __expf(x.w) : 0.f;
            sum += (e0 + e1) + (e2 + e3);
        }
    }
    sum = warpSum(sum);
    const float inv = 1.f / sum;

    // ---- P2: recompute exp, scan + decay + exp2 + sum2, q -> smem ----
    float carry = 0.f;
    float s2 = 0.f;
    for (int c = 0; c < nch; c++) {
        int j = c * 128 + lane * 4;
        float4 x = *(const float4*)&row[j];
        float fj = (float)j;
        float e0, e1, e2, e3;
        if (c < ci) {
            e0 = __expf(x.x); e1 = __expf(x.y);
            e2 = __expf(x.z); e3 = __expf(x.w);
        } else {
            e0 = (fj       <= fi) ? __expf(x.x) : 0.f;
            e1 = (fj + 1.f <= fi) ? __expf(x.y) : 0.f;
            e2 = (fj + 2.f <= fi) ? __expf(x.z) : 0.f;
            e3 = (fj + 3.f <= fi) ? __expf(x.w) : 0.f;
        }
        float t = (e0 + e1) + (e2 + e3);
        float incl = t;
        #pragma unroll
        for (int o = 1; o < 32; o <<= 1) {
            float tt = __shfl_up_sync(0xffffffffu, incl, o);
            if (lane >= o) incl += tt;
        }
        float base = carry + (incl - t);
        carry += __shfl_sync(0xffffffffu, incl, 31);

        float p0 = base + e0, p1 = p0 + e1, p2 = p1 + e2, p3 = p2 + e3;
        float d0 = sqrtf(fmaxf((1.f - p0 * inv) * (fi - fj),       0.f));
        float d1 = sqrtf(fmaxf((1.f - p1 * inv) * (fi - fj - 1.f), 0.f));
        float d2 = sqrtf(fmaxf((1.f - p2 * inv) * (fi - fj - 2.f), 0.f));
        float d3 = sqrtf(fmaxf((1.f - p3 * inv) * (fi - fj - 3.f), 0.f));
        float f0 = fminf(fmaxf(__expf(d0 * gamma), 1e-5f), 1e5f);
        float f1 = fminf(fmaxf(__expf(d1 * gamma), 1e-5f), 1e5f);
        float f2 = fminf(fmaxf(__expf(d2 * gamma), 1e-5f), 1e5f);
        float f3 = fminf(fmaxf(__expf(d3 * gamma), 1e-5f), 1e5f);
        float4 qv;
        qv.x = (e0 > 0.f) ? __expf(x.x * f0) : 0.f;
        qv.y = (e1 > 0.f) ? __expf(x.y * f1) : 0.f;
        qv.z = (e2 > 0.f) ? __expf(x.z * f2) : 0.f;
        qv.w = (e3 > 0.f) ? __expf(x.w * f3) : 0.f;
        s2 += (qv.x + qv.y) + (qv.z + qv.w);
        *(float4*)&row[j] = qv;
    }
    s2 = warpSum(s2);
    const float inv2 = 1.f / s2;

    // ---- P3: normalize + bf16 hi/lo split store ----
    for (int c = 0; c < nch; c++) {
        int j = c * 128 + lane * 4;
        float4 qv = *(const float4*)&row[j];
        float p0 = qv.x * inv2, p1 = qv.y * inv2;
        float p2 = qv.z * inv2, p3 = qv.w * inv2;
        __nv_bfloat16 h0 = __float2bfloat16(p0), h1 = __float2bfloat16(p1);
        __nv_bfloat16 h2 = __float2bfloat16(p2), h3 = __float2bfloat16(p3);
        __nv_bfloat162 hh0(h0, h1), hh1(h2, h3);
        __nv_bfloat162 ll0(__float2bfloat16(p0 - __bfloat162float(h0)),
                           __float2bfloat16(p1 - __bfloat162float(h1)));
        __nv_bfloat162 ll1(__float2bfloat16(p2 - __bfloat162float(h2)),
                           __float2bfloat16(p3 - __bfloat162float(h3)));
        *(__nv_bfloat162*)(dh + j)     = hh0;
        *(__nv_bfloat162*)(dh + j + 2) = hh1;
        *(__nv_bfloat162*)(dl + j)     = ll0;
        *(__nv_bfloat162*)(dl + j + 2) = ll1;
    }
}

// ============================================================================
// PV kernel v4: tile 64(i) x 64(d), cp.async DOUBLE-BUFFERED, 3 CTAs/SM.
// Per-stage smem: Ph|Pl|Vh|Vl 64x144 each = 36864 B; x2 stages = 73728 B.
// it reversed so heavy tiles (njc up to 16) launch first.
// ============================================================================
#define PVT 9216      // 64*144
#define PV_STAGE (4*PVT)
#define PV_SMEM (2*PV_STAGE)

__global__ __launch_bounds__(256, 3)
void pv_kernel()
{
    extern __shared__ char sm[];
    const uint32_t sb = smem_u32(sm);
    const int it = 15 - blockIdx.x;    // heavy tiles first
    const int z = blockIdx.y;
    const int tid = threadIdx.x;
    const int wid = tid >> 5;
    const int lane = tid & 31;

    const int i0 = it * 64;
    const int wm = (wid >> 2) * 32;    // 2 warp rows x 32
    const int wn = (wid & 3) * 16;     // 4 warp cols x 16

    const __nv_bfloat16* Ph = g_ph + ((long)z << 20);
    const __nv_bfloat16* Pl = g_pl + ((long)z << 20);
    const __nv_bfloat16* Vh = g_vth + (long)z * DD * SS;
    const __nv_bfloat16* Vl = g_vtl + (long)z * DD * SS;

    float c[2][2][4];
    #pragma unroll
    for (int a = 0; a < 2; a++)
        #pragma unroll
        for (int b = 0; b < 2; b++)
            #pragma unroll
            for (int d = 0; d < 4; d++) c[a][b][d] = 0.f;

    const int njc = it + 1;            // 64-j chunks, causal

    // precompute this thread's staging role (same for every chunk)
    const int slot0 = tid;             // 2 iters: tid, tid+256... 8 total
    // stage(jc, buf): issue cp.async for chunk jc into buffer buf
    auto stage = [&](int jc, int buf) {
        const uint32_t bufb = sb + buf * PV_STAGE;
        #pragma unroll
        for (int i = 0; i < 8; i++) {
            int slot = slot0 + i * 256;        // 0..2047
            int arr = slot >> 9;               // 0:Ph 1:Pl 2:Vh 3:Vl
            int r   = (slot >> 3) & 63;
            int cg  = slot & 7;
            uint32_t dst = bufb + arr * PVT + r * TPAD + cg * 16;
            const __nv_bfloat16* src;
            long off;
            if (arr < 2) {
                src = arr ? Pl : Ph;
                off = (long)(i0 + r) * SS + jc*64 + cg*8;
            } else {
                src = (arr == 3) ? Vl : Vh;
                off = (long)r * SS + jc*64 + cg*8;
            }
            CPASYNC16(dst, src + off);
        }
        CPCOMMIT();
    };

    stage(0, 0);
    for (int jc = 0; jc < njc; jc++) {
        const int buf = jc & 1;
        if (jc + 1 < njc) {
            stage(jc + 1, buf ^ 1);
            CPWAIT(1);                 // chunk jc's group complete
        } else {
            CPWAIT(0);
        }
        __syncthreads();

        const uint32_t bufb = sb + buf * PV_STAGE;
        #pragma unroll
        for (int ks = 0; ks < 4; ks++) {
            uint32_t bh[2][2], bl[2][2];
            #pragma unroll
            for (int ni = 0; ni < 2; ni++) {
                uint32_t addr = (uint32_t)((wn + ni*8 + (lane & 7)) * TPAD
                               + (ks*16 + ((lane >> 3) & 1) * 8) * 2);
                ldsm_x2(bh[ni], bufb + 2*PVT + addr);
                ldsm_x2(bl[ni], bufb + 3*PVT + addr);
            }
            #pragma unroll
            for (int mi = 0; mi < 2; mi++) {
                uint32_t addr = (uint32_t)((wm + mi*16 + (lane & 15)) * TPAD
                               + (ks*16 + (lane >> 4) * 8) * 2);
                uint32_t ah[4], al[4];
                ldsm_x4(ah, bufb + addr);
                ldsm_x4(al, bufb + PVT + addr);
                #pragma unroll
                for (int ni = 0; ni < 2; ni++) {
                    mma_bf16(c[mi][ni], ah, bh[ni]);
                    mma_bf16(c[mi][ni], ah, bl[ni]);
                    mma_bf16(c[mi][ni], al, bh[ni]);
                }
            }
        }
        __syncthreads();               // done reading buf before re-stage
    }

    const int b = z >> 3, h = z & 7;
    const int qrow = lane >> 2;
    const int qcol = (lane & 3) * 2;
    #pragma unroll
    for (int mi = 0; mi < 2; mi++) {
        #pragma unroll
        for (int ni = 0; ni < 2; ni++) {
            #pragma unroll
            for (int half = 0; half < 2; half++) {
                int s = i0 + wm + mi*16 + qrow + half*8;
                int e = h*DD + wn + ni*8 + qcol;
                long idx = ((long)(b*SS + s)) * EE + e;
                float x0 = c[mi][ni][half*2 + 0];
                float x1 = c[mi][ni][half*2 + 1];
                __nv_bfloat16 h0 = __float2bfloat16(x0);
                __nv_bfloat16 h1 = __float2bfloat16(x1);
                *(__nv_bfloat162*)&g_aoh[idx] = __nv_bfloat162(h0, h1);
                *(__nv_bfloat162*)&g_aol[idx] = __nv_bfloat162(
                    __float2bfloat16(x0 - __bfloat162float(h0)),
                    __float2bfloat16(x1 - __bfloat162float(h1)));
            }
        }
    }
}

// ============================================================================
extern "C" void kernel_launch(void* const* d_in, const int* in_sizes, int n_in,
                              void* d_out, int out_size)
{
    const float* q      = (const float*)d_in[0];
    const float* k      = (const float*)d_in[1];
    const float* v      = (const float*)d_in[2];
    const float* Wk     = (const float*)d_in[3];
    const float* bk     = (const float*)d_in[4];
    const float* Wv     = (const float*)d_in[5];
    const float* bv     = (const float*)d_in[6];
    const float* Wo     = (const float*)d_in[7];
    const float* bo     = (const float*)d_in[8];
    const float* gammas = (const float*)d_in[9];
    float* out = (float*)d_out;

    cudaFuncSetAttribute(gemm_bf16, cudaFuncAttributeMaxDynamicSharedMemorySize,
                         GEMM_SMEM);
    cudaFuncSetAttribute(scores_kernel, cudaFuncAttributeMaxDynamicSharedMemorySize,
                         SCORES_SMEM);
    cudaFuncSetAttribute(pv_kernel, cudaFuncAttributeMaxDynamicSharedMemorySize,
                         PV_SMEM);

    gemm_bf16<<<dim3(64, 4, 3), 256, GEMM_SMEM>>>(q, k, v, Wk, Wv, Wo,
                                                  bk, bv, bo, out, 0);
    scores_kernel<<<dim3(NTILES, 64), 256, SCORES_SMEM>>>();
    softmax_kernel<<<64*1024/8, 256>>>(gammas);
    pv_kernel<<<dim3(16, 64), 256, PV_SMEM>>>();
    gemm_bf16<<<dim3(64, 4, 1), 256, GEMM_SMEM>>>(q, k, v, Wk, Wv, Wo,
                                                  bk, bv, bo, out, 1);
}

// round 15
// speedup vs baseline: 1.0345x; 1.0345x over previous
#include <cuda_runtime.h>
#include <cuda_bf16.h>
#include <math.h>
#include <stdint.h>

#define BB 8
#define SS 1024
#define EE 512
#define HH 8
#define DD 64

// ---------------- scratch (__device__ globals; no allocation) ---------------
__device__ __nv_bfloat16 g_qbh[BB*HH*SS*DD];   // projected Q heads bf16 hi/lo
__device__ __nv_bfloat16 g_qbl[BB*HH*SS*DD];
__device__ __nv_bfloat16 g_kbh[BB*HH*SS*DD];   // projected K heads
__device__ __nv_bfloat16 g_kbl[BB*HH*SS*DD];
__device__ __nv_bfloat16 g_vth[BB*HH*DD*SS];   // projected V, TRANSPOSED [z][d][s]
__device__ __nv_bfloat16 g_vtl[BB*HH*DD*SS];
__device__ float         g_sc[64L*SS*SS];      // scores [z][i][j] fp32 (256MB)
__device__ __nv_bfloat16 g_ph[64L*SS*SS];      // probs bf16 hi
__device__ __nv_bfloat16 g_pl[64L*SS*SS];      // probs bf16 lo
__device__ __nv_bfloat16 g_aoh[8192L*512];     // attention out hi
__device__ __nv_bfloat16 g_aol[8192L*512];     // attention out lo

// ---------------- helpers ---------------------------------------------------
__device__ __forceinline__ uint32_t smem_u32(const void* p) {
    uint32_t a;
    asm("{ .reg .u64 t; cvta.to.shared.u64 t, %1; cvt.u32.u64 %0, t; }"
        : "=r"(a) : "l"(p));
    return a;
}
__device__ __forceinline__ void ldsm_x4(uint32_t r[4], uint32_t addr) {
    asm volatile("ldmatrix.sync.aligned.m8n8.x4.shared.b16 {%0,%1,%2,%3}, [%4];"
        : "=r"(r[0]), "=r"(r[1]), "=r"(r[2]), "=r"(r[3]) : "r"(addr));
}
__device__ __forceinline__ void ldsm_x2(uint32_t r[2], uint32_t addr) {
    asm volatile("ldmatrix.sync.aligned.m8n8.x2.shared.b16 {%0,%1}, [%2];"
        : "=r"(r[0]), "=r"(r[1]) : "r"(addr));
}
__device__ __forceinline__ void mma_bf16(float c[4], const uint32_t a[4],
                                         const uint32_t b[2]) {
    asm volatile(
        "mma.sync.aligned.m16n8k16.row.col.f32.bf16.bf16.f32 "
        "{%0,%1,%2,%3}, {%4,%5,%6,%7}, {%8,%9}, {%0,%1,%2,%3};"
        : "+f"(c[0]), "+f"(c[1]), "+f"(c[2]), "+f"(c[3])
        : "r"(a[0]), "r"(a[1]), "r"(a[2]), "r"(a[3]), "r"(b[0]), "r"(b[1]));
}
__device__ __forceinline__ float warpSum(float v) {
    #pragma unroll
    for (int o = 16; o > 0; o >>= 1) v += __shfl_xor_sync(0xffffffffu, v, o);
    return v;
}
// fp32x4 -> bf16 hi/lo pairs (each 8 bytes)
__device__ __forceinline__ void split4(float4 x, __nv_bfloat162& h0,
                                       __nv_bfloat162& h1,
                                       __nv_bfloat162& l0,
                                       __nv_bfloat162& l1) {
    __nv_bfloat16 a = __float2bfloat16(x.x), b = __float2bfloat16(x.y);
    __nv_bfloat16 c = __float2bfloat16(x.z), d = __float2bfloat16(x.w);
    h0 = __nv_bfloat162(a, b);
    h1 = __nv_bfloat162(c, d);
    l0 = __nv_bfloat162(__float2bfloat16(x.x - __bfloat162float(a)),
                        __float2bfloat16(x.y - __bfloat162float(b)));
    l1 = __nv_bfloat162(__float2bfloat16(x.z - __bfloat162float(c)),
                        __float2bfloat16(x.w - __bfloat162float(d)));
}

#define TPAD 144
#define TILE64 9216    // 64*144

// ============================================================================
// Tensor-core GEMM v2 (3x bf16 split), tile 64x64, 3 CTAs/SM.
//   mode 0 (z): A = q/k/v fp32 (split in staging), B = Wk/Wk/Wv fp32;
//               C -> bf16 hi/lo head layout (z==2: V transposed [z][d][s])
//   mode 1:     A = g_aoh/g_aol bf16, B = Wo fp32; C -> fp32 out
// smem: Ah|Al|Bh|Bl 64x144 each = 36864 B.
// ============================================================================
#define GEMM_SMEM (4*TILE64)

__global__ __launch_bounds__(256, 3)
void gemm_bf16(const float* __restrict__ q, const float* __restrict__ k,
               const float* __restrict__ v,
               const float* __restrict__ Wk, const float* __restrict__ Wv,
               const float* __restrict__ Wo,
               const float* __restrict__ bk, const float* __restrict__ bv,
               const float* __restrict__ bo, float* __restrict__ out, int mode)
{
    extern __shared__ char sm[];
    const uint32_t sb = smem_u32(sm);
    const int tid = threadIdx.x;
    const int wid = tid >> 5;
    const int lane = tid & 31;

    const float *X = 0, *W;
    const float* bias;
    __nv_bfloat16 *Ybh = 0, *Ybl = 0;
    int z = 0;
    if (mode == 0) {
        z = blockIdx.z;
        X = (z == 0) ? q : ((z == 1) ? k : v);
        W = (z == 2) ? Wv : Wk;
        bias = (z == 2) ? bv : bk;
        Ybh = (z == 0) ? g_qbh : ((z == 1) ? g_kbh : g_vth);
        Ybl = (z == 0) ? g_qbl : ((z == 1) ? g_kbl : g_vtl);
    } else {
        W = Wo;
        bias = bo;
    }

    const int m0 = blockIdx.x * 64;
    const int n0 = blockIdx.y * 64;
    const int wm = (wid >> 2) * 32;    // 2 warp rows x 32
    const int wn = (wid & 3) * 16;     // 4 warp cols x 16

    float c[2][2][4];
    #pragma unroll
    for (int a = 0; a < 2; a++)
        #pragma unroll
        for (int b = 0; b < 2; b++)
            #pragma unroll
            for (int d = 0; d < 4; d++) c[a][b][d] = 0.f;

    for (int ch = 0; ch < 8; ch++) {
        __syncthreads();
        if (mode == 0) {
            // A and B tiles 64x64 fp32 -> hi/lo: 2048 float4 slots
            #pragma unroll
            for (int i = 0; i < 8; i++) {
                int slot = tid + i * 256;          // 0..2047
                int arr2 = slot >> 10;             // 0:A 1:B
                int r    = (slot >> 4) & 63;
                int g    = slot & 15;
                const float* src = arr2 ? W : X;
                int grow = (arr2 ? n0 : m0) + r;
                float4 x = *(const float4*)(src + (long)grow * 512 + ch * 64 + g * 4);
                __nv_bfloat162 h0, h1, l0, l1;
                split4(x, h0, h1, l0, l1);
                char* hb = sm + arr2 * (2*TILE64) + r * TPAD + g * 8;
                *(__nv_bfloat162*)(hb)              = h0;
                *(__nv_bfloat162*)(hb + 4)          = h1;
                *(__nv_bfloat162*)(hb + TILE64)     = l0;
                *(__nv_bfloat162*)(hb + TILE64 + 4) = l1;
            }
        } else {
            // A: bf16 hi/lo copy (1024 uint4 slots); B: fp32 split (1024)
            #pragma unroll
            for (int i = 0; i < 8; i++) {
                int slot = tid + i * 256;
                if (slot < 1024) {
                    int arr = slot >> 9;           // 0:hi 1:lo
                    int r   = (slot >> 3) & 63;
                    int cg  = slot & 7;
                    const __nv_bfloat16* src = arr ? g_aol : g_aoh;
                    uint4 v4 = *(const uint4*)(src + (long)(m0 + r) * 512
                                               + ch * 64 + cg * 8);
                    *(uint4*)(sm + arr * TILE64 + r * TPAD + cg * 16) = v4;
                } else {
                    int s2 = slot - 1024;
                    int r  = (s2 >> 4) & 63;
                    int g  = s2 & 15;
                    float4 x = *(const float4*)(W + (long)(n0 + r) * 512
                                                + ch * 64 + g * 4);
                    __nv_bfloat162 h0, h1, l0, l1;
                    split4(x, h0, h1, l0, l1);
                    char* hb = sm + 2*TILE64 + r * TPAD + g * 8;
                    *(__nv_bfloat162*)(hb)              = h0;
                    *(__nv_bfloat162*)(hb + 4)          = h1;
                    *(__nv_bfloat162*)(hb + TILE64)     = l0;
                    *(__nv_bfloat162*)(hb + TILE64 + 4) = l1;
                }
            }
        }
        __syncthreads();

        #pragma unroll
        for (int ks = 0; ks < 4; ks++) {
            uint32_t bh[2][2], bl[2][2];
            #pragma unroll
            for (int ni = 0; ni < 2; ni++) {
                uint32_t addr = (uint32_t)((wn + ni*8 + (lane & 7)) * TPAD
                               + (ks*16 + ((lane >> 3) & 1) * 8) * 2);
                ldsm_x2(bh[ni], sb + 2*TILE64 + addr);
                ldsm_x2(bl[ni], sb + 3*TILE64 + addr);
            }
            #pragma unroll
            for (int mi = 0; mi < 2; mi++) {
                uint32_t addr = (uint32_t)((wm + mi*16 + (lane & 15)) * TPAD
                               + (ks*16 + (lane >> 4) * 8) * 2);
                uint32_t ah[4], al[4];
                ldsm_x4(ah, sb + addr);
                ldsm_x4(al, sb + TILE64 + addr);
                #pragma unroll
                for (int ni = 0; ni < 2; ni++) {
                    mma_bf16(c[mi][ni], ah, bh[ni]);
                    mma_bf16(c[mi][ni], ah, bl[ni]);
                    mma_bf16(c[mi][ni], al, bh[ni]);
                }
            }
        }
    }

    const int qrow = lane >> 2;
    const int qcol = (lane & 3) * 2;
    #pragma unroll
    for (int mi = 0; mi < 2; mi++) {
        #pragma unroll
        for (int ni = 0; ni < 2; ni++) {
            #pragma unroll
            for (int half = 0; half < 2; half++) {
                int m  = m0 + wm + mi*16 + qrow + half*8;
                int cn = n0 + wn + ni*8 + qcol;
                float x0 = c[mi][ni][half*2 + 0] + bias[cn];
                float x1 = c[mi][ni][half*2 + 1] + bias[cn + 1];
                __nv_bfloat16 h0 = __float2bfloat16(x0);
                __nv_bfloat16 h1 = __float2bfloat16(x1);
                __nv_bfloat16 l0 = __float2bfloat16(x0 - __bfloat162float(h0));
                __nv_bfloat16 l1 = __float2bfloat16(x1 - __bfloat162float(h1));
                if (mode == 0) {
                    int b = m >> 10, s = m & 1023;
                    int h = cn >> 6, d = cn & 63;
                    if (z == 2) {   // V: transposed [z][d][s]
                        long ti = ((long)(b*HH + h) * DD + d) * SS + s;
                        Ybh[ti] = h0;      Ybl[ti] = l0;
                        Ybh[ti + SS] = h1; Ybl[ti + SS] = l1;
                    } else {
                        long idx = (((long)(b*HH + h)) * SS + s) * DD + d;
                        *(__nv_bfloat162*)&Ybh[idx] = __nv_bfloat162(h0, h1);
                        *(__nv_bfloat162*)&Ybl[idx] = __nv_bfloat162(l0, l1);
                    }
                } else {
                    *(float2*)&out[(long)m * 512 + cn] = make_float2(x0, x1);
                }
            }
        }
    }
}

// ============================================================================
// Scores kernel: triangular grid — blockIdx.x = linear causal tile index.
// ============================================================================
#define TSZ  18432     // 128*144
#define SCORES_SMEM (4*TSZ)
#define NTILES 36      // 8*9/2

__global__ __launch_bounds__(256, 1)
void scores_kernel()
{
    const int t = blockIdx.x, z = blockIdx.y;
    int it = (int)((sqrtf(8.f * t + 1.f) - 1.f) * 0.5f);
    while ((it + 1) * (it + 2) / 2 <= t) ++it;
    while (it * (it + 1) / 2 > t) --it;
    const int jt = t - it * (it + 1) / 2;

    extern __shared__ char sm[];
    const uint32_t sb = smem_u32(sm);
    const int tid = threadIdx.x;
    const int wid = tid >> 5;
    const int lane = tid & 31;

    const long base = (long)z * SS * DD;
    const __nv_bfloat16* Qh = g_qbh + base;
    const __nv_bfloat16* Ql = g_qbl + base;
    const __nv_bfloat16* Kh = g_kbh + base;
    const __nv_bfloat16* Kl = g_kbl + base;

    const int m0 = it * 128;
    const int n0 = jt * 128;
    const int wm = (wid >> 2) * 64;
    const int wn = (wid & 3) * 32;

    #pragma unroll
    for (int i = 0; i < 16; i++) {
        int slot = tid + i * 256;
        int arr  = slot >> 10;
        int r    = (slot >> 3) & 127;
        int cg   = slot & 7;
        const __nv_bfloat16* src =
            (arr == 0) ? Qh : ((arr == 1) ? Ql : ((arr == 2) ? Kh : Kl));
        int grow = ((arr < 2) ? m0 : n0) + r;
        uint4 v4 = *(const uint4*)(src + (long)grow * DD + cg * 8);
        *(uint4*)(sm + arr * TSZ + r * TPAD + cg * 16) = v4;
    }
    __syncthreads();

    float c[4][4][4];
    #pragma unroll
    for (int a = 0; a < 4; a++)
        #pragma unroll
        for (int b = 0; b < 4; b++)
            #pragma unroll
            for (int d = 0; d < 4; d++) c[a][b][d] = 0.f;

    #pragma unroll
    for (int ks = 0; ks < 4; ks++) {
        uint32_t bh[4][2], bl[4][2];
        #pragma unroll
        for (int ni = 0; ni < 4; ni++) {
            uint32_t addr = (uint32_t)((wn + ni*8 + (lane & 7)) * TPAD
                           + (ks*16 + ((lane >> 3) & 1) * 8) * 2);
            ldsm_x2(bh[ni], sb + 2*TSZ + addr);
            ldsm_x2(bl[ni], sb + 3*TSZ + addr);
        }
        #pragma unroll
        for (int mi = 0; mi < 4; mi++) {
            uint32_t addr = (uint32_t)((wm + mi*16 + (lane & 15)) * TPAD
                           + (ks*16 + (lane >> 4) * 8) * 2);
            uint32_t ah[4], al[4];
            ldsm_x4(ah, sb + addr);
            ldsm_x4(al, sb + TSZ + addr);
            #pragma unroll
            for (int ni = 0; ni < 4; ni++) {
                mma_bf16(c[mi][ni], ah, bh[ni]);
                mma_bf16(c[mi][ni], ah, bl[ni]);
                mma_bf16(c[mi][ni], al, bh[ni]);
            }
        }
    }

    float* dst = g_sc + ((long)z << 20);
    const int qrow = lane >> 2;
    const int qcol = (lane & 3) * 2;
    #pragma unroll
    for (int mi = 0; mi < 4; mi++) {
        #pragma unroll
        for (int ni = 0; ni < 4; ni++) {
            #pragma unroll
            for (int half = 0; half < 2; half++) {
                int m  = m0 + wm + mi*16 + qrow + half*8;
                int cn = n0 + wn + ni*8 + qcol;
                float2 o;
                o.x = c[mi][ni][half*2 + 0] * 0.125f;
                o.y = c[mi][ni][half*2 + 1] * 0.125f;
                *(float2*)&dst[(long)m * SS + cn] = o;
            }
        }
    }
}

// ============================================================================
// Softmax kernel v5 (R11): smem-row-resident, no max-subtraction, 3 passes.
// ============================================================================
__global__ __launch_bounds__(256)
void softmax_kernel(const float* __restrict__ gammas)
{
    __shared__ float rows[8][1024];
    const int tid = threadIdx.x;
    const int w = tid >> 5;
    const int lane = tid & 31;
    float* row = rows[w];

    const long gr = (long)(gridDim.x - 1 - blockIdx.x) * 8 + w;
    const int z = (int)(gr >> 10);
    const int i = (int)(gr & 1023);
    const long rbase = ((long)z << 20) + ((long)i << 10);
    __nv_bfloat16* dh = g_ph + rbase;
    __nv_bfloat16* dl = g_pl + rbase;

    if (i == 0) {
        if (lane < 16) {
            *(uint4*)(dh + lane * 8) = make_uint4(0u, 0u, 0u, 0u);
            *(uint4*)(dl + lane * 8) = make_uint4(0u, 0u, 0u, 0u);
        }
        return;
    }

    const float gamma = -log1pf(expf(gammas[z & 7]));
    const float fi = (float)i;
    const int ci = i >> 7;
    const int nch = ci + 1;

    // ---- P1: load -> smem, exp + sum (mask only in chunk ci) ----
    float sum = 0.f;
    for (int c = 0; c < nch; c++) {
        int j = c * 128 + lane * 4;
        float4 x = *(const float4*)(g_sc + rbase + j);
        *(float4*)&row[j] = x;
        if (c < ci) {
            sum += (__expf(x.x) + __expf(x.y)) + (__expf(x.z) + __expf(x.w));
        } else {
            float fj = (float)j;
            float e0 = (fj       <= fi) ? __expf(x.x) : 0.f;
            float e1 = (fj + 1.f <= fi) ? __expf(x.y) : 0.f;
            float e2 = (fj + 2.f <= fi) ? __expf(x.z) : 0.f;
            float e3 = (fj + 3.f <= fi) ? __expf(x.w) : 0.f;
            sum += (e0 + e1) + (e2 + e3);
        }
    }
    sum = warpSum(sum);
    const float inv = 1.f / sum;

    // ---- P2: recompute exp, scan + decay + exp2 + sum2, q -> smem ----
    float carry = 0.f;
    float s2 = 0.f;
    for (int c = 0; c < nch; c++) {
        int j = c * 128 + lane * 4;
        float4 x = *(const float4*)&row[j];
        float fj = (float)j;
        float e0, e1, e2, e3;
        if (c < ci) {
            e0 = __expf(x.x); e1 = __expf(x.y);
            e2 = __expf(x.z); e3 = __expf(x.w);
        } else {
            e0 = (fj       <= fi) ? __expf(x.x) : 0.f;
            e1 = (fj + 1.f <= fi) ? __expf(x.y) : 0.f;
            e2 = (fj + 2.f <= fi) ? __expf(x.z) : 0.f;
            e3 = (fj + 3.f <= fi) ? __expf(x.w) : 0.f;
        }
        float t = (e0 + e1) + (e2 + e3);
        float incl = t;
        #pragma unroll
        for (int o = 1; o < 32; o <<= 1) {
            float tt = __shfl_up_sync(0xffffffffu, incl, o);
            if (lane >= o) incl += tt;
        }
        float base = carry + (incl - t);
        carry += __shfl_sync(0xffffffffu, incl, 31);

        float p0 = base + e0, p1 = p0 + e1, p2 = p1 + e2, p3 = p2 + e3;
        float d0 = sqrtf(fmaxf((1.f - p0 * inv) * (fi - fj),       0.f));
        float d1 = sqrtf(fmaxf((1.f - p1 * inv) * (fi - fj - 1.f), 0.f));
        float d2 = sqrtf(fmaxf((1.f - p2 * inv) * (fi - fj - 2.f), 0.f));
        float d3 = sqrtf(fmaxf((1.f - p3 * inv) * (fi - fj - 3.f), 0.f));
        float f0 = fminf(fmaxf(__expf(d0 * gamma), 1e-5f), 1e5f);
        float f1 = fminf(fmaxf(__expf(d1 * gamma), 1e-5f), 1e5f);
        float f2 = fminf(fmaxf(__expf(d2 * gamma), 1e-5f), 1e5f);
        float f3 = fminf(fmaxf(__expf(d3 * gamma), 1e-5f), 1e5f);
        float4 qv;
        qv.x = (e0 > 0.f) ? __expf(x.x * f0) : 0.f;
        qv.y = (e1 > 0.f) ? __expf(x.y * f1) : 0.f;
        qv.z = (e2 > 0.f) ? __expf(x.z * f2) : 0.f;
        qv.w = (e3 > 0.f) ? __expf(x.w * f3) : 0.f;
        s2 += (qv.x + qv.y) + (qv.z + qv.w);
        *(float4*)&row[j] = qv;
    }
    s2 = warpSum(s2);
    const float inv2 = 1.f / s2;

    // ---- P3: normalize + bf16 hi/lo split store ----
    for (int c = 0; c < nch; c++) {
        int j = c * 128 + lane * 4;
        float4 qv = *(const float4*)&row[j];
        float p0 = qv.x * inv2, p1 = qv.y * inv2;
        float p2 = qv.z * inv2, p3 = qv.w * inv2;
        __nv_bfloat16 h0 = __float2bfloat16(p0), h1 = __float2bfloat16(p1);
        __nv_bfloat16 h2 = __float2bfloat16(p2), h3 = __float2bfloat16(p3);
        __nv_bfloat162 hh0(h0, h1), hh1(h2, h3);
        __nv_bfloat162 ll0(__float2bfloat16(p0 - __bfloat162float(h0)),
                           __float2bfloat16(p1 - __bfloat162float(h1)));
        __nv_bfloat162 ll1(__float2bfloat16(p2 - __bfloat162float(h2)),
                           __float2bfloat16(p3 - __bfloat162float(h3)));
        *(__nv_bfloat162*)(dh + j)     = hh0;
        *(__nv_bfloat162*)(dh + j + 2) = hh1;
        *(__nv_bfloat162*)(dl + j)     = ll0;
        *(__nv_bfloat162*)(dl + j + 2) = ll1;
    }
}

// ============================================================================
// PV kernel (R13 version): tile 64(i) x 64(d), single-buffer, 3 CTAs/SM.
// ============================================================================
#define PVT 9216      // 64*144
#define PV_SMEM (4*PVT)

__global__ __launch_bounds__(256, 3)
void pv_kernel()
{
    extern __shared__ char sm[];
    const uint32_t sb = smem_u32(sm);
    const int it = 15 - blockIdx.x;    // heavy tiles first
    const int z = blockIdx.y;
    const int tid = threadIdx.x;
    const int wid = tid >> 5;
    const int lane = tid & 31;

    const int i0 = it * 64;
    const int wm = (wid >> 2) * 32;
    const int wn = (wid & 3) * 16;

    const __nv_bfloat16* Ph = g_ph + ((long)z << 20);
    const __nv_bfloat16* Pl = g_pl + ((long)z << 20);
    const __nv_bfloat16* Vh = g_vth + (long)z * DD * SS;
    const __nv_bfloat16* Vl = g_vtl + (long)z * DD * SS;

    float c[2][2][4];
    #pragma unroll
    for (int a = 0; a < 2; a++)
        #pragma unroll
        for (int b = 0; b < 2; b++)
            #pragma unroll
            for (int d = 0; d < 4; d++) c[a][b][d] = 0.f;

    const int njc = it + 1;
    for (int jc = 0; jc < njc; jc++) {
        __syncthreads();
        #pragma unroll
        for (int i = 0; i < 8; i++) {
            int slot = tid + i * 256;
            int arr = slot >> 9;               // 0:Ph 1:Pl 2:Vh 3:Vl
            int r   = (slot >> 3) & 63;
            int cg  = slot & 7;
            uint4 v4;
            if (arr < 2) {
                const __nv_bfloat16* src = arr ? Pl : Ph;
                v4 = *(const uint4*)(src + (long)(i0 + r) * SS + jc*64 + cg*8);
            } else {
                const __nv_bfloat16* src = (arr == 3) ? Vl : Vh;
                v4 = *(const uint4*)(src + (long)r * SS + jc*64 + cg*8);
            }
            *(uint4*)(sm + arr * PVT + r * TPAD + cg * 16) = v4;
        }
        __syncthreads();

        #pragma unroll
        for (int ks = 0; ks < 4; ks++) {
            uint32_t bh[2][2], bl[2][2];
            #pragma unroll
            for (int ni = 0; ni < 2; ni++) {
                uint32_t addr = (uint32_t)((wn + ni*8 + (lane & 7)) * TPAD
                               + (ks*16 + ((lane >> 3) & 1) * 8) * 2);
                ldsm_x2(bh[ni], sb + 2*PVT + addr);
                ldsm_x2(bl[ni], sb + 3*PVT + addr);
            }
            #pragma unroll
            for (int mi = 0; mi < 2; mi++) {
                uint32_t addr = (uint32_t)((wm + mi*16 + (lane & 15)) * TPAD
                               + (ks*16 + (lane >> 4) * 8) * 2);
                uint32_t ah[4], al[4];
                ldsm_x4(ah, sb + addr);
                ldsm_x4(al, sb + PVT + addr);
                #pragma unroll
                for (int ni = 0; ni < 2; ni++) {
                    mma_bf16(c[mi][ni], ah, bh[ni]);
                    mma_bf16(c[mi][ni], ah, bl[ni]);
                    mma_bf16(c[mi][ni], al, bh[ni]);
                }
            }
        }
    }

    const int b = z >> 3, h = z & 7;
    const int qrow = lane >> 2;
    const int qcol = (lane & 3) * 2;
    #pragma unroll
    for (int mi = 0; mi < 2; mi++) {
        #pragma unroll
        for (int ni = 0; ni < 2; ni++) {
            #pragma unroll
            for (int half = 0; half < 2; half++) {
                int s = i0 + wm + mi*16 + qrow + half*8;
                int e = h*DD + wn + ni*8 + qcol;
                long idx = ((long)(b*SS + s)) * EE + e;
                float x0 = c[mi][ni][half*2 + 0];
                float x1 = c[mi][ni][half*2 + 1];
                __nv_bfloat16 h0 = __float2bfloat16(x0);
                __nv_bfloat16 h1 = __float2bfloat16(x1);
                *(__nv_bfloat162*)&g_aoh[idx] = __nv_bfloat162(h0, h1);
                *(__nv_bfloat162*)&g_aol[idx] = __nv_bfloat162(
                    __float2bfloat16(x0 - __bfloat162float(h0)),
                    __float2bfloat16(x1 - __bfloat162float(h1)));
            }
        }
    }
}

// ============================================================================
extern "C" void kernel_launch(void* const* d_in, const int* in_sizes, int n_in,
                              void* d_out, int out_size)
{
    const float* q      = (const float*)d_in[0];
    const float* k      = (const float*)d_in[1];
    const float* v      = (const float*)d_in[2];
    const float* Wk     = (const float*)d_in[3];
    const float* bk     = (const float*)d_in[4];
    const float* Wv     = (const float*)d_in[5];
    const float* bv     = (const float*)d_in[6];
    const float* Wo     = (const float*)d_in[7];
    const float* bo     = (const float*)d_in[8];
    const float* gammas = (const float*)d_in[9];
    float* out = (float*)d_out;

    cudaFuncSetAttribute(gemm_bf16, cudaFuncAttributeMaxDynamicSharedMemorySize,
                         GEMM_SMEM);
    cudaFuncSetAttribute(scores_kernel, cudaFuncAttributeMaxDynamicSharedMemorySize,
                         SCORES_SMEM);
    cudaFuncSetAttribute(pv_kernel, cudaFuncAttributeMaxDynamicSharedMemorySize,
                         PV_SMEM);

    gemm_bf16<<<dim3(128, 8, 3), 256, GEMM_SMEM>>>(q, k, v, Wk, Wv, Wo,
                                                   bk, bv, bo, out, 0);
    scores_kernel<<<dim3(NTILES, 64), 256, SCORES_SMEM>>>();
    softmax_kernel<<<64*1024/8, 256>>>(gammas);
    pv_kernel<<<dim3(16, 64), 256, PV_SMEM>>>();
    gemm_bf16<<<dim3(128, 8), 256, GEMM_SMEM>>>(q, k, v, Wk, Wv, Wo,
                                                bk, bv, bo, out, 1);
}

// round 16
// speedup vs baseline: 1.0521x; 1.0171x over previous
#include <cuda_runtime.h>
#include <cuda_bf16.h>
#include <math.h>
#include <stdint.h>

#define BB 8
#define SS 1024
#define EE 512
#define HH 8
#define DD 64

// ---------------- scratch (__device__ globals; no allocation) ---------------
__device__ __nv_bfloat16 g_qbh[BB*HH*SS*DD];   // projected Q heads bf16 hi/lo
__device__ __nv_bfloat16 g_qbl[BB*HH*SS*DD];
__device__ __nv_bfloat16 g_kbh[BB*HH*SS*DD];   // projected K heads
__device__ __nv_bfloat16 g_kbl[BB*HH*SS*DD];
__device__ __nv_bfloat16 g_vth[BB*HH*DD*SS];   // projected V, TRANSPOSED [z][d][s]
__device__ __nv_bfloat16 g_vtl[BB*HH*DD*SS];
__device__ float         g_sc[64L*SS*SS];      // scores [z][i][j] fp32 (256MB)
__device__ __nv_bfloat16 g_ph[64L*SS*SS];      // UNNORMALIZED probs bf16 hi
__device__ __nv_bfloat16 g_pl[64L*SS*SS];      // UNNORMALIZED probs bf16 lo
__device__ float         g_s2inv[64L*SS];      // per-row 1/sum2 (0 for row 0)
__device__ __nv_bfloat16 g_aoh[8192L*512];     // attention out hi
__device__ __nv_bfloat16 g_aol[8192L*512];     // attention out lo

// ---------------- helpers ---------------------------------------------------
__device__ __forceinline__ uint32_t smem_u32(const void* p) {
    uint32_t a;
    asm("{ .reg .u64 t; cvta.to.shared.u64 t, %1; cvt.u32.u64 %0, t; }"
        : "=r"(a) : "l"(p));
    return a;
}
__device__ __forceinline__ void ldsm_x4(uint32_t r[4], uint32_t addr) {
    asm volatile("ldmatrix.sync.aligned.m8n8.x4.shared.b16 {%0,%1,%2,%3}, [%4];"
        : "=r"(r[0]), "=r"(r[1]), "=r"(r[2]), "=r"(r[3]) : "r"(addr));
}
__device__ __forceinline__ void ldsm_x2(uint32_t r[2], uint32_t addr) {
    asm volatile("ldmatrix.sync.aligned.m8n8.x2.shared.b16 {%0,%1}, [%2];"
        : "=r"(r[0]), "=r"(r[1]) : "r"(addr));
}
__device__ __forceinline__ void mma_bf16(float c[4], const uint32_t a[4],
                                         const uint32_t b[2]) {
    asm volatile(
        "mma.sync.aligned.m16n8k16.row.col.f32.bf16.bf16.f32 "
        "{%0,%1,%2,%3}, {%4,%5,%6,%7}, {%8,%9}, {%0,%1,%2,%3};"
        : "+f"(c[0]), "+f"(c[1]), "+f"(c[2]), "+f"(c[3])
        : "r"(a[0]), "r"(a[1]), "r"(a[2]), "r"(a[3]), "r"(b[0]), "r"(b[1]));
}
__device__ __forceinline__ float warpSum(float v) {
    #pragma unroll
    for (int o = 16; o > 0; o >>= 1) v += __shfl_xor_sync(0xffffffffu, v, o);
    return v;
}
// fp32x4 -> bf16 hi/lo pairs (each 8 bytes)
__device__ __forceinline__ void split4(float4 x, __nv_bfloat162& h0,
                                       __nv_bfloat162& h1,
                                       __nv_bfloat162& l0,
                                       __nv_bfloat162& l1) {
    __nv_bfloat16 a = __float2bfloat16(x.x), b = __float2bfloat16(x.y);
    __nv_bfloat16 c = __float2bfloat16(x.z), d = __float2bfloat16(x.w);
    h0 = __nv_bfloat162(a, b);
    h1 = __nv_bfloat162(c, d);
    l0 = __nv_bfloat162(__float2bfloat16(x.x - __bfloat162float(a)),
                        __float2bfloat16(x.y - __bfloat162float(b)));
    l1 = __nv_bfloat162(__float2bfloat16(x.z - __bfloat162float(c)),
                        __float2bfloat16(x.w - __bfloat162float(d)));
}

#define TPAD 144
#define TILE64 9216    // 64*144

// ============================================================================
// Tensor-core GEMM (3x bf16 split), tile 64x64, 3 CTAs/SM.  (R15 version)
// ============================================================================
#define GEMM_SMEM (4*TILE64)

__global__ __launch_bounds__(256, 3)
void gemm_bf16(const float* __restrict__ q, const float* __restrict__ k,
               const float* __restrict__ v,
               const float* __restrict__ Wk, const float* __restrict__ Wv,
               const float* __restrict__ Wo,
               const float* __restrict__ bk, const float* __restrict__ bv,
               const float* __restrict__ bo, float* __restrict__ out, int mode)
{
    extern __shared__ char sm[];
    const uint32_t sb = smem_u32(sm);
    const int tid = threadIdx.x;
    const int wid = tid >> 5;
    const int lane = tid & 31;

    const float *X = 0, *W;
    const float* bias;
    __nv_bfloat16 *Ybh = 0, *Ybl = 0;
    int z = 0;
    if (mode == 0) {
        z = blockIdx.z;
        X = (z == 0) ? q : ((z == 1) ? k : v);
        W = (z == 2) ? Wv : Wk;
        bias = (z == 2) ? bv : bk;
        Ybh = (z == 0) ? g_qbh : ((z == 1) ? g_kbh : g_vth);
        Ybl = (z == 0) ? g_qbl : ((z == 1) ? g_kbl : g_vtl);
    } else {
        W = Wo;
        bias = bo;
    }

    const int m0 = blockIdx.x * 64;
    const int n0 = blockIdx.y * 64;
    const int wm = (wid >> 2) * 32;
    const int wn = (wid & 3) * 16;

    float c[2][2][4];
    #pragma unroll
    for (int a = 0; a < 2; a++)
        #pragma unroll
        for (int b = 0; b < 2; b++)
            #pragma unroll
            for (int d = 0; d < 4; d++) c[a][b][d] = 0.f;

    for (int ch = 0; ch < 8; ch++) {
        __syncthreads();
        if (mode == 0) {
            #pragma unroll
            for (int i = 0; i < 8; i++) {
                int slot = tid + i * 256;
                int arr2 = slot >> 10;
                int r    = (slot >> 4) & 63;
                int g    = slot & 15;
                const float* src = arr2 ? W : X;
                int grow = (arr2 ? n0 : m0) + r;
                float4 x = *(const float4*)(src + (long)grow * 512 + ch * 64 + g * 4);
                __nv_bfloat162 h0, h1, l0, l1;
                split4(x, h0, h1, l0, l1);
                char* hb = sm + arr2 * (2*TILE64) + r * TPAD + g * 8;
                *(__nv_bfloat162*)(hb)              = h0;
                *(__nv_bfloat162*)(hb + 4)          = h1;
                *(__nv_bfloat162*)(hb + TILE64)     = l0;
                *(__nv_bfloat162*)(hb + TILE64 + 4) = l1;
            }
        } else {
            #pragma unroll
            for (int i = 0; i < 8; i++) {
                int slot = tid + i * 256;
                if (slot < 1024) {
                    int arr = slot >> 9;
                    int r   = (slot >> 3) & 63;
                    int cg  = slot & 7;
                    const __nv_bfloat16* src = arr ? g_aol : g_aoh;
                    uint4 v4 = *(const uint4*)(src + (long)(m0 + r) * 512
                                               + ch * 64 + cg * 8);
                    *(uint4*)(sm + arr * TILE64 + r * TPAD + cg * 16) = v4;
                } else {
                    int s2 = slot - 1024;
                    int r  = (s2 >> 4) & 63;
                    int g  = s2 & 15;
                    float4 x = *(const float4*)(W + (long)(n0 + r) * 512
                                                + ch * 64 + g * 4);
                    __nv_bfloat162 h0, h1, l0, l1;
                    split4(x, h0, h1, l0, l1);
                    char* hb = sm + 2*TILE64 + r * TPAD + g * 8;
                    *(__nv_bfloat162*)(hb)              = h0;
                    *(__nv_bfloat162*)(hb + 4)          = h1;
                    *(__nv_bfloat162*)(hb + TILE64)     = l0;
                    *(__nv_bfloat162*)(hb + TILE64 + 4) = l1;
                }
            }
        }
        __syncthreads();

        #pragma unroll
        for (int ks = 0; ks < 4; ks++) {
            uint32_t bh[2][2], bl[2][2];
            #pragma unroll
            for (int ni = 0; ni < 2; ni++) {
                uint32_t addr = (uint32_t)((wn + ni*8 + (lane & 7)) * TPAD
                               + (ks*16 + ((lane >> 3) & 1) * 8) * 2);
                ldsm_x2(bh[ni], sb + 2*TILE64 + addr);
                ldsm_x2(bl[ni], sb + 3*TILE64 + addr);
            }
            #pragma unroll
            for (int mi = 0; mi < 2; mi++) {
                uint32_t addr = (uint32_t)((wm + mi*16 + (lane & 15)) * TPAD
                               + (ks*16 + (lane >> 4) * 8) * 2);
                uint32_t ah[4], al[4];
                ldsm_x4(ah, sb + addr);
                ldsm_x4(al, sb + TILE64 + addr);
                #pragma unroll
                for (int ni = 0; ni < 2; ni++) {
                    mma_bf16(c[mi][ni], ah, bh[ni]);
                    mma_bf16(c[mi][ni], ah, bl[ni]);
                    mma_bf16(c[mi][ni], al, bh[ni]);
                }
            }
        }
    }

    const int qrow = lane >> 2;
    const int qcol = (lane & 3) * 2;
    #pragma unroll
    for (int mi = 0; mi < 2; mi++) {
        #pragma unroll
        for (int ni = 0; ni < 2; ni++) {
            #pragma unroll
            for (int half = 0; half < 2; half++) {
                int m  = m0 + wm + mi*16 + qrow + half*8;
                int cn = n0 + wn + ni*8 + qcol;
                float x0 = c[mi][ni][half*2 + 0] + bias[cn];
                float x1 = c[mi][ni][half*2 + 1] + bias[cn + 1];
                __nv_bfloat16 h0 = __float2bfloat16(x0);
                __nv_bfloat16 h1 = __float2bfloat16(x1);
                __nv_bfloat16 l0 = __float2bfloat16(x0 - __bfloat162float(h0));
                __nv_bfloat16 l1 = __float2bfloat16(x1 - __bfloat162float(h1));
                if (mode == 0) {
                    int b = m >> 10, s = m & 1023;
                    int h = cn >> 6, d = cn & 63;
                    if (z == 2) {
                        long ti = ((long)(b*HH + h) * DD + d) * SS + s;
                        Ybh[ti] = h0;      Ybl[ti] = l0;
                        Ybh[ti + SS] = h1; Ybl[ti + SS] = l1;
                    } else {
                        long idx = (((long)(b*HH + h)) * SS + s) * DD + d;
                        *(__nv_bfloat162*)&Ybh[idx] = __nv_bfloat162(h0, h1);
                        *(__nv_bfloat162*)&Ybl[idx] = __nv_bfloat162(l0, l1);
                    }
                } else {
                    *(float2*)&out[(long)m * 512 + cn] = make_float2(x0, x1);
                }
            }
        }
    }
}

// ============================================================================
// Scores kernel v2: tile 64x64, triangular 64-grain grid, 3 CTAs/SM.
// smem: Qh|Ql|Kh|Kl 64x144 each = 36864 B. Uniform work per CTA.
// ============================================================================
#define SCORES_SMEM (4*TILE64)
#define NT64 136      // 16*17/2

__global__ __launch_bounds__(256, 3)
void scores_kernel()
{
    const int t = blockIdx.x, z = blockIdx.y;
    int it = (int)((sqrtf(8.f * t + 1.f) - 1.f) * 0.5f);
    while ((it + 1) * (it + 2) / 2 <= t) ++it;
    while (it * (it + 1) / 2 > t) --it;
    const int jt = t - it * (it + 1) / 2;

    extern __shared__ char sm[];
    const uint32_t sb = smem_u32(sm);
    const int tid = threadIdx.x;
    const int wid = tid >> 5;
    const int lane = tid & 31;

    const long base = (long)z * SS * DD;
    const int m0 = it * 64;
    const int n0 = jt * 64;
    const int wm = (wid >> 2) * 32;
    const int wn = (wid & 3) * 16;

    #pragma unroll
    for (int i = 0; i < 8; i++) {
        int slot = tid + i * 256;          // 0..2047
        int arr  = slot >> 9;              // 0:Qh 1:Ql 2:Kh 3:Kl
        int r    = (slot >> 3) & 63;
        int cg   = slot & 7;
        const __nv_bfloat16* src =
            (arr == 0) ? g_qbh : ((arr == 1) ? g_qbl :
            ((arr == 2) ? g_kbh : g_kbl));
        int grow = ((arr < 2) ? m0 : n0) + r;
        uint4 v4 = *(const uint4*)(src + base + (long)grow * DD + cg * 8);
        *(uint4*)(sm + arr * TILE64 + r * TPAD + cg * 16) = v4;
    }
    __syncthreads();

    float c[2][2][4];
    #pragma unroll
    for (int a = 0; a < 2; a++)
        #pragma unroll
        for (int b = 0; b < 2; b++)
            #pragma unroll
            for (int d = 0; d < 4; d++) c[a][b][d] = 0.f;

    #pragma unroll
    for (int ks = 0; ks < 4; ks++) {
        uint32_t bh[2][2], bl[2][2];
        #pragma unroll
        for (int ni = 0; ni < 2; ni++) {
            uint32_t addr = (uint32_t)((wn + ni*8 + (lane & 7)) * TPAD
                           + (ks*16 + ((lane >> 3) & 1) * 8) * 2);
            ldsm_x2(bh[ni], sb + 2*TILE64 + addr);
            ldsm_x2(bl[ni], sb + 3*TILE64 + addr);
        }
        #pragma unroll
        for (int mi = 0; mi < 2; mi++) {
            uint32_t addr = (uint32_t)((wm + mi*16 + (lane & 15)) * TPAD
                           + (ks*16 + (lane >> 4) * 8) * 2);
            uint32_t ah[4], al[4];
            ldsm_x4(ah, sb + addr);
            ldsm_x4(al, sb + TILE64 + addr);
            #pragma unroll
            for (int ni = 0; ni < 2; ni++) {
                mma_bf16(c[mi][ni], ah, bh[ni]);
                mma_bf16(c[mi][ni], ah, bl[ni]);
                mma_bf16(c[mi][ni], al, bh[ni]);
            }
        }
    }

    float* dst = g_sc + ((long)z << 20);
    const int qrow = lane >> 2;
    const int qcol = (lane & 3) * 2;
    #pragma unroll
    for (int mi = 0; mi < 2; mi++) {
        #pragma unroll
        for (int ni = 0; ni < 2; ni++) {
            #pragma unroll
            for (int half = 0; half < 2; half++) {
                int m  = m0 + wm + mi*16 + qrow + half*8;
                int cn = n0 + wn + ni*8 + qcol;
                float2 o;
                o.x = c[mi][ni][half*2 + 0] * 0.125f;
                o.y = c[mi][ni][half*2 + 1] * 0.125f;
                *(float2*)&dst[(long)m * SS + cn] = o;
            }
        }
    }
}

// ============================================================================
// Softmax kernel v6: 2 passes + deferred normalization.
//   P1: gmem load -> smem, exp + sum
//   P2: recompute exp, scan + decay + exp2 + sum2; store UNNORMALIZED q
//       bf16 hi/lo straight to gmem. Then store 1/sum2 per row to g_s2inv.
// ============================================================================
__global__ __launch_bounds__(256)
void softmax_kernel(const float* __restrict__ gammas)
{
    __shared__ float rows[8][1024];
    const int tid = threadIdx.x;
    const int w = tid >> 5;
    const int lane = tid & 31;
    float* row = rows[w];

    const long gr = (long)(gridDim.x - 1 - blockIdx.x) * 8 + w;
    const int z = (int)(gr >> 10);
    const int i = (int)(gr & 1023);
    const long rbase = ((long)z << 20) + ((long)i << 10);
    __nv_bfloat16* dh = g_ph + rbase;
    __nv_bfloat16* dl = g_pl + rbase;

    if (i == 0) {   // zero_pad: zero probs; scale 0 (finite, row is zero anyway)
        if (lane < 16) {
            *(uint4*)(dh + lane * 8) = make_uint4(0u, 0u, 0u, 0u);
            *(uint4*)(dl + lane * 8) = make_uint4(0u, 0u, 0u, 0u);
        }
        if (lane == 0) g_s2inv[gr] = 0.f;
        return;
    }

    const float gamma = -log1pf(expf(gammas[z & 7]));
    const float fi = (float)i;
    const int ci = i >> 7;
    const int nch = ci + 1;

    // ---- P1: load -> smem, exp + sum (mask only in chunk ci) ----
    float sum = 0.f;
    for (int c = 0; c < nch; c++) {
        int j = c * 128 + lane * 4;
        float4 x = *(const float4*)(g_sc + rbase + j);
        *(float4*)&row[j] = x;
        if (c < ci) {
            sum += (__expf(x.x) + __expf(x.y)) + (__expf(x.z) + __expf(x.w));
        } else {
            float fj = (float)j;
            float e0 = (fj       <= fi) ? __expf(x.x) : 0.f;
            float e1 = (fj + 1.f <= fi) ? __expf(x.y) : 0.f;
            float e2 = (fj + 2.f <= fi) ? __expf(x.z) : 0.f;
            float e3 = (fj + 3.f <= fi) ? __expf(x.w) : 0.f;
            sum += (e0 + e1) + (e2 + e3);
        }
    }
    sum = warpSum(sum);
    const float inv = 1.f / sum;

    // ---- P2: recompute exp, scan + decay + exp2 + sum2; store q hi/lo ----
    float carry = 0.f;
    float s2 = 0.f;
    for (int c = 0; c < nch; c++) {
        int j = c * 128 + lane * 4;
        float4 x = *(const float4*)&row[j];
        float fj = (float)j;
        float e0, e1, e2, e3;
        if (c < ci) {
            e0 = __expf(x.x); e1 = __expf(x.y);
            e2 = __expf(x.z); e3 = __expf(x.w);
        } else {
            e0 = (fj       <= fi) ? __expf(x.x) : 0.f;
            e1 = (fj + 1.f <= fi) ? __expf(x.y) : 0.f;
            e2 = (fj + 2.f <= fi) ? __expf(x.z) : 0.f;
            e3 = (fj + 3.f <= fi) ? __expf(x.w) : 0.f;
        }
        float t = (e0 + e1) + (e2 + e3);
        float incl = t;
        #pragma unroll
        for (int o = 1; o < 32; o <<= 1) {
            float tt = __shfl_up_sync(0xffffffffu, incl, o);
            if (lane >= o) incl += tt;
        }
        float base = carry + (incl - t);
        carry += __shfl_sync(0xffffffffu, incl, 31);

        float p0 = base + e0, p1 = p0 + e1, p2 = p1 + e2, p3 = p2 + e3;
        float d0 = sqrtf(fmaxf((1.f - p0 * inv) * (fi - fj),       0.f));
        float d1 = sqrtf(fmaxf((1.f - p1 * inv) * (fi - fj - 1.f), 0.f));
        float d2 = sqrtf(fmaxf((1.f - p2 * inv) * (fi - fj - 2.f), 0.f));
        float d3 = sqrtf(fmaxf((1.f - p3 * inv) * (fi - fj - 3.f), 0.f));
        float f0 = fminf(fmaxf(__expf(d0 * gamma), 1e-5f), 1e5f);
        float f1 = fminf(fmaxf(__expf(d1 * gamma), 1e-5f), 1e5f);
        float f2 = fminf(fmaxf(__expf(d2 * gamma), 1e-5f), 1e5f);
        float f3 = fminf(fmaxf(__expf(d3 * gamma), 1e-5f), 1e5f);
        float q0 = (e0 > 0.f) ? __expf(x.x * f0) : 0.f;
        float q1 = (e1 > 0.f) ? __expf(x.y * f1) : 0.f;
        float q2 = (e2 > 0.f) ? __expf(x.z * f2) : 0.f;
        float q3 = (e3 > 0.f) ? __expf(x.w * f3) : 0.f;
        s2 += (q0 + q1) + (q2 + q3);
        // store unnormalized q, bf16 hi/lo
        __nv_bfloat16 h0 = __float2bfloat16(q0), h1 = __float2bfloat16(q1);
        __nv_bfloat16 h2 = __float2bfloat16(q2), h3 = __float2bfloat16(q3);
        __nv_bfloat162 hh0(h0, h1), hh1(h2, h3);
        __nv_bfloat162 ll0(__float2bfloat16(q0 - __bfloat162float(h0)),
                           __float2bfloat16(q1 - __bfloat162float(h1)));
        __nv_bfloat162 ll1(__float2bfloat16(q2 - __bfloat162float(h2)),
                           __float2bfloat16(q3 - __bfloat162float(h3)));
        *(__nv_bfloat162*)(dh + j)     = hh0;
        *(__nv_bfloat162*)(dh + j + 2) = hh1;
        *(__nv_bfloat162*)(dl + j)     = ll0;
        *(__nv_bfloat162*)(dl + j + 2) = ll1;
    }
    s2 = warpSum(s2);
    if (lane == 0) g_s2inv[gr] = 1.f / s2;
}

// ============================================================================
// PV kernel v5: tile 64(i) x 64(d), 3 CTAs/SM; per-row scale in epilogue.
// ============================================================================
#define PVT 9216      // 64*144
#define PV_SMEM (4*PVT + 256)

__global__ __launch_bounds__(256, 3)
void pv_kernel()
{
    extern __shared__ char sm[];
    const uint32_t sb = smem_u32(sm);
    float* sinv = (float*)(sm + 4*PVT);
    const int it = 15 - blockIdx.x;    // heavy tiles first
    const int z = blockIdx.y;
    const int tid = threadIdx.x;
    const int wid = tid >> 5;
    const int lane = tid & 31;

    const int i0 = it * 64;
    const int wm = (wid >> 2) * 32;
    const int wn = (wid & 3) * 16;

    const __nv_bfloat16* Ph = g_ph + ((long)z << 20);
    const __nv_bfloat16* Pl = g_pl + ((long)z << 20);
    const __nv_bfloat16* Vh = g_vth + (long)z * DD * SS;
    const __nv_bfloat16* Vl = g_vtl + (long)z * DD * SS;

    if (tid < 64) sinv[tid] = g_s2inv[(long)z * SS + i0 + tid];

    float c[2][2][4];
    #pragma unroll
    for (int a = 0; a < 2; a++)
        #pragma unroll
        for (int b = 0; b < 2; b++)
            #pragma unroll
            for (int d = 0; d < 4; d++) c[a][b][d] = 0.f;

    const int njc = it + 1;
    for (int jc = 0; jc < njc; jc++) {
        __syncthreads();
        #pragma unroll
        for (int i = 0; i < 8; i++) {
            int slot = tid + i * 256;
            int arr = slot >> 9;               // 0:Ph 1:Pl 2:Vh 3:Vl
            int r   = (slot >> 3) & 63;
            int cg  = slot & 7;
            uint4 v4;
            if (arr < 2) {
                const __nv_bfloat16* src = arr ? Pl : Ph;
                v4 = *(const uint4*)(src + (long)(i0 + r) * SS + jc*64 + cg*8);
            } else {
                const __nv_bfloat16* src = (arr == 3) ? Vl : Vh;
                v4 = *(const uint4*)(src + (long)r * SS + jc*64 + cg*8);
            }
            *(uint4*)(sm + arr * PVT + r * TPAD + cg * 16) = v4;
        }
        __syncthreads();

        #pragma unroll
        for (int ks = 0; ks < 4; ks++) {
            uint32_t bh[2][2], bl[2][2];
            #pragma unroll
            for (int ni = 0; ni < 2; ni++) {
                uint32_t addr = (uint32_t)((wn + ni*8 + (lane & 7)) * TPAD
                               + (ks*16 + ((lane >> 3) & 1) * 8) * 2);
                ldsm_x2(bh[ni], sb + 2*PVT + addr);
                ldsm_x2(bl[ni], sb + 3*PVT + addr);
            }
            #pragma unroll
            for (int mi = 0; mi < 2; mi++) {
                uint32_t addr = (uint32_t)((wm + mi*16 + (lane & 15)) * TPAD
                               + (ks*16 + (lane >> 4) * 8) * 2);
                uint32_t ah[4], al[4];
                ldsm_x4(ah, sb + addr);
                ldsm_x4(al, sb + PVT + addr);
                #pragma unroll
                for (int ni = 0; ni < 2; ni++) {
                    mma_bf16(c[mi][ni], ah, bh[ni]);
                    mma_bf16(c[mi][ni], ah, bl[ni]);
                    mma_bf16(c[mi][ni], al, bh[ni]);
                }
            }
        }
    }

    const int b = z >> 3, h = z & 7;
    const int qrow = lane >> 2;
    const int qcol = (lane & 3) * 2;
    #pragma unroll
    for (int mi = 0; mi < 2; mi++) {
        #pragma unroll
        for (int ni = 0; ni < 2; ni++) {
            #pragma unroll
            for (int half = 0; half < 2; half++) {
                int sr = wm + mi*16 + qrow + half*8;       // row in tile
                int s = i0 + sr;
                int e = h*DD + wn + ni*8 + qcol;
                long idx = ((long)(b*SS + s)) * EE + e;
                float sc = sinv[sr];
                float x0 = c[mi][ni][half*2 + 0] * sc;
                float x1 = c[mi][ni][half*2 + 1] * sc;
                __nv_bfloat16 h0 = __float2bfloat16(x0);
                __nv_bfloat16 h1 = __float2bfloat16(x1);
                *(__nv_bfloat162*)&g_aoh[idx] = __nv_bfloat162(h0, h1);
                *(__nv_bfloat162*)&g_aol[idx] = __nv_bfloat162(
                    __float2bfloat16(x0 - __bfloat162float(h0)),
                    __float2bfloat16(x1 - __bfloat162float(h1)));
            }
        }
    }
}

// ============================================================================
extern "C" void kernel_launch(void* const* d_in, const int* in_sizes, int n_in,
                              void* d_out, int out_size)
{
    const float* q      = (const float*)d_in[0];
    const float* k      = (const float*)d_in[1];
    const float* v      = (const float*)d_in[2];
    const float* Wk     = (const float*)d_in[3];
    const float* bk     = (const float*)d_in[4];
    const float* Wv     = (const float*)d_in[5];
    const float* bv     = (const float*)d_in[6];
    const float* Wo     = (const float*)d_in[7];
    const float* bo     = (const float*)d_in[8];
    const float* gammas = (const float*)d_in[9];
    float* out = (float*)d_out;

    cudaFuncSetAttribute(gemm_bf16, cudaFuncAttributeMaxDynamicSharedMemorySize,
                         GEMM_SMEM);
    cudaFuncSetAttribute(scores_kernel, cudaFuncAttributeMaxDynamicSharedMemorySize,
                         SCORES_SMEM);
    cudaFuncSetAttribute(pv_kernel, cudaFuncAttributeMaxDynamicSharedMemorySize,
                         PV_SMEM);

    gemm_bf16<<<dim3(128, 8, 3), 256, GEMM_SMEM>>>(q, k, v, Wk, Wv, Wo,
                                                   bk, bv, bo, out, 0);
    scores_kernel<<<dim3(NT64, 64), 256, SCORES_SMEM>>>();
    softmax_kernel<<<64*1024/8, 256>>>(gammas);
    pv_kernel<<<dim3(16, 64), 256, PV_SMEM>>>();
    gemm_bf16<<<dim3(128, 8), 256, GEMM_SMEM>>>(q, k, v, Wk, Wv, Wo,
                                                bk, bv, bo, out, 1);
}